// round 17
// baseline (speedup 1.0000x reference)
#include <cuda_runtime.h>
#include <cuda_bf16.h>

// DE_NN_35820027249305: per-l tiny MLP chain (1 -> 4 -> 8 -> 4 -> 1, ReLU)
// over X of shape (44, 1, 400000).
//
// Collapse (input channel dim = 1, ReLU positively homogeneous):
//   out = x * (x >= 0 ? S_plus[l] : -S_minus[l])
// with the 88 scalars depending only on the weights.
//
// R15: exact tiling — TPB=160, VPT=5 => 800 float4/block, 125 blocks per l
// (100000 = 125*800). Zero bounds checks / predicates. Barrier-free per-warp
// distributed scale computation (R10 win) retained: lanes 0-15 sign +,
// 16-31 sign -; one q_j per lane, shfl reductions, two final broadcasts.
// Epilogue is the 3-op select form x * (x>=0 ? c0 : c1).

#define NP_L   44
#define B_ELEM 400000
#define B_VEC4 (B_ELEM / 4)        // 100000 float4 per l
#define VPT    5                   // float4 per thread
#define TPB    160                 // 5 warps
#define F4_PER_BLOCK (TPB * VPT)   // 800  -> 125 blocks per l, exact

__global__ void __launch_bounds__(TPB)
DE_NN_fused_kernel(const float* __restrict__ X,
                   const float* __restrict__ lin1,   // (44, 4, 1)
                   const float* __restrict__ lin2,   // (44, 8, 4)
                   const float* __restrict__ lin3,   // (44, 4, 8)
                   const float* __restrict__ lin4,   // (44, 1, 4)
                   float* __restrict__ out)
{
    const int l    = blockIdx.y;
    const int base = blockIdx.x * F4_PER_BLOCK + threadIdx.x;

    const float4* __restrict__ xp =
        reinterpret_cast<const float4*>(X + (size_t)l * B_ELEM) + base;
    float4* __restrict__ op =
        reinterpret_cast<float4*>(out + (size_t)l * B_ELEM) + base;

    // ---- 1. Issue all X loads first (front-batched, MLP_p1 = 5) ----------
    float4 v[VPT];
    #pragma unroll
    for (int i = 0; i < VPT; i++)
        v[i] = xp[i * TPB];

    // ---- 2. Per-warp distributed collapsed network (no smem, no barrier) -
    // Lanes 0-15 evaluate sign +, lanes 16-31 sign -.
    const int   lane = threadIdx.x & 31;
    const int   grp  = lane >> 4;            // 0: +, 1: -
    const int   gb   = grp << 4;             // group base lane
    const float sign = grp ? -1.0f : 1.0f;

    // Layer 1 (warp-broadcast load)
    const float4 w1 = *reinterpret_cast<const float4*>(lin1 + l * 4);
    const float p0 = fmaxf(sign * w1.x, 0.0f);
    const float p1 = fmaxf(sign * w1.y, 0.0f);
    const float p2 = fmaxf(sign * w1.z, 0.0f);
    const float p3 = fmaxf(sign * w1.w, 0.0f);

    // Layer 2: lane gb+j (j = lane&7) computes q_j
    const float4 w2 = reinterpret_cast<const float4*>(lin2 + l * 32)[lane & 7];
    float q = w2.x * p0;
    q = fmaf(w2.y, p1, q);
    q = fmaf(w2.z, p2, q);
    q = fmaf(w2.w, p3, q);
    q = fmaxf(q, 0.0f);

    // Layer 3: lane gb+k (k = lane&3) reduces r_k via shuffles
    const float* w3row = lin3 + l * 32 + (lane & 3) * 8;
    float r = 0.0f;
    #pragma unroll
    for (int j = 0; j < 8; j++) {
        const float qj = __shfl_sync(0xffffffffu, q, gb + j);
        r = fmaf(w3row[j], qj, r);
    }
    r = fmaxf(r, 0.0f);

    // Layer 4: every lane reduces its group's S
    const float* w4 = lin4 + l * 4;
    float S = 0.0f;
    #pragma unroll
    for (int k = 0; k < 4; k++) {
        const float rk = __shfl_sync(0xffffffffu, r, gb + k);
        S = fmaf(w4[k], rk, S);
    }

    // Broadcast both group results to all lanes.
    const float c0 = __shfl_sync(0xffffffffu, S, 0);    // S(+1)
    const float c1 = -__shfl_sync(0xffffffffu, S, 16);  // -S(-1)

    // ---- 3. 3-op select epilogue + stores (no predicates) ----------------
    #pragma unroll
    for (int i = 0; i < VPT; i++) {
        const float4 x = v[i];
        float4 o;
        o.x = x.x * (x.x >= 0.0f ? c0 : c1);
        o.y = x.y * (x.y >= 0.0f ? c0 : c1);
        o.z = x.z * (x.z >= 0.0f ? c0 : c1);
        o.w = x.w * (x.w >= 0.0f ? c0 : c1);
        op[i * TPB] = o;
    }
}

extern "C" void kernel_launch(void* const* d_in, const int* in_sizes, int n_in,
                              void* d_out, int out_size)
{
    const float* X  = (const float*)d_in[0];
    const float* l1 = (const float*)d_in[1];
    const float* l2 = (const float*)d_in[2];
    const float* l3 = (const float*)d_in[3];
    const float* l4 = (const float*)d_in[4];
    float* out      = (float*)d_out;

    dim3 grid(B_VEC4 / F4_PER_BLOCK, NP_L);   // (125, 44), exact cover
    DE_NN_fused_kernel<<<grid, TPB>>>(X, l1, l2, l3, l4, out);
}